// round 2
// baseline (speedup 1.0000x reference)
#include <cuda_runtime.h>
#include <cstdint>
#include <math_constants.h>

#define NMAX 100000
#define EMAX 3200000
#define CH 64
#define BMAX 512
#define KTOP 30
#define PLEN 1950   // 30 * 65
#define SEGMAX 4096

// ---------------- scratch (static device globals; no allocs allowed) -------
__device__ float g_xw1[NMAX * CH];   // x @ W1
__device__ float g_y[NMAX * CH];     // xw1 * dis (pre-scaled source msg)
__device__ float g_x1[NMAX * CH];    // tanh conv1 output
__device__ float g_dis[NMAX];
__device__ float g_xw2[NMAX];
__device__ float g_z[NMAX];          // xw2 * dis
__device__ float g_x2[NMAX];
__device__ int   g_indeg[NMAX];
__device__ int   g_estart[NMAX + 1];
__device__ int   g_cursor[NMAX];
__device__ int   g_srow[EMAX];       // edge sources sorted by destination
__device__ int   g_cnt[BMAX];
__device__ int   g_start[BMAX];

// ---------------- K1: xw1 = x @ W1 (100000x128 @ 128x64) -------------------
#define GEMM_TR 128
#define XPITCH 132
#define GEMM_SMEM ((GEMM_TR * XPITCH + 128 * 64) * 4)

__global__ void gemm1_kernel(const float* __restrict__ x,
                             const float* __restrict__ W, int n) {
    extern __shared__ float smem[];
    float* xs = smem;                       // [128][132]
    float* ws = smem + GEMM_TR * XPITCH;    // [128][64]
    int t = threadIdx.x;
    int row0 = blockIdx.x * GEMM_TR;

    for (int i = t; i < 128 * 64 / 4; i += 256)
        ((float4*)ws)[i] = ((const float4*)W)[i];
    for (int i = t; i < GEMM_TR * 32; i += 256) {
        int r = i >> 5, c4 = i & 31;
        float4 v = make_float4(0.f, 0.f, 0.f, 0.f);
        if (row0 + r < n) v = ((const float4*)x)[(size_t)(row0 + r) * 32 + c4];
        *(float4*)&xs[r * XPITCH + c4 * 4] = v;
    }
    __syncthreads();

    int tx = t & 7;
    int ty = t >> 3;
    float acc[4][8];
#pragma unroll
    for (int i = 0; i < 4; i++)
#pragma unroll
        for (int j = 0; j < 8; j++) acc[i][j] = 0.f;

#pragma unroll 4
    for (int k = 0; k < 128; k++) {
        float4 b0 = *(float4*)&ws[k * 64 + tx * 8];
        float4 b1 = *(float4*)&ws[k * 64 + tx * 8 + 4];
        float bb[8] = {b0.x, b0.y, b0.z, b0.w, b1.x, b1.y, b1.z, b1.w};
        float aa[4];
#pragma unroll
        for (int i = 0; i < 4; i++) aa[i] = xs[(ty * 4 + i) * XPITCH + k];
#pragma unroll
        for (int i = 0; i < 4; i++)
#pragma unroll
            for (int j = 0; j < 8; j++) acc[i][j] += aa[i] * bb[j];
    }

#pragma unroll
    for (int i = 0; i < 4; i++) {
        int r = row0 + ty * 4 + i;
        if (r < n) {
            *(float4*)&g_xw1[(size_t)r * 64 + tx * 8] =
                make_float4(acc[i][0], acc[i][1], acc[i][2], acc[i][3]);
            *(float4*)&g_xw1[(size_t)r * 64 + tx * 8 + 4] =
                make_float4(acc[i][4], acc[i][5], acc[i][6], acc[i][7]);
        }
    }
}

// ---------------- K2: in-degree counts (non-self edges) --------------------
__global__ void indeg_kernel(const int* __restrict__ row,
                             const int* __restrict__ col, int E) {
    int e = blockIdx.x * blockDim.x + threadIdx.x;
    if (e >= E) return;
    int r = row[e], c = col[e];
    if (r != c) atomicAdd(&g_indeg[c], 1);
}

// ---------------- K3: single-block exclusive scan of indeg -> estart/cursor -
__global__ void node_scan_kernel(int n) {
    __shared__ int s[1024];
    int t = threadIdx.x;
    int chunk = (n + 1023) >> 10;
    int s0 = min(t * chunk, n);
    int s1 = min(s0 + chunk, n);
    int sum = 0;
    for (int i = s0; i < s1; i++) sum += g_indeg[i];
    s[t] = sum;
    __syncthreads();
    // Hillis-Steele inclusive scan over 1024
    for (int off = 1; off < 1024; off <<= 1) {
        int u = (t >= off) ? s[t - off] : 0;
        __syncthreads();
        s[t] += u;
        __syncthreads();
    }
    int off = s[t] - sum;  // exclusive prefix of this thread's chunk
    for (int i = s0; i < s1; i++) {
        g_estart[i] = off;
        g_cursor[i] = off;
        off += g_indeg[i];
    }
    if (s1 == n && s0 <= n) g_estart[n] = off;
}

// ---------------- K4: scatter edges into dest-sorted list ------------------
__global__ void scatter_kernel(const int* __restrict__ row,
                               const int* __restrict__ col, int E) {
    int e = blockIdx.x * blockDim.x + threadIdx.x;
    if (e >= E) return;
    int r = row[e], c = col[e];
    if (r == c) return;
    int pos = atomicAdd(&g_cursor[c], 1);
    g_srow[pos] = r;
}

// ---------------- K5: dis, y = xw1*dis, batch counts ------------------------
__global__ void prep_kernel(const int* __restrict__ batch, int n) {
    int t = blockIdx.x * blockDim.x + threadIdx.x;
    int node = t >> 4, sub = t & 15;
    if (node >= n) return;
    float dis = rsqrtf((float)g_indeg[node] + 1.0f);
    if (sub == 0) {
        g_dis[node] = dis;
        atomicAdd(&g_cnt[batch[node]], 1);
    }
    float4 v = ((const float4*)&g_xw1[(size_t)node * 64])[sub];
    v.x *= dis; v.y *= dis; v.z *= dis; v.w *= dis;
    ((float4*)&g_y[(size_t)node * 64])[sub] = v;
}

// ---------------- K6: gather-aggregate conv1 + tanh + W2 dot (fused) --------
__global__ void agg1_gather_kernel(const float* __restrict__ b1,
                                   const float* __restrict__ W2, int n) {
    int wg = (blockIdx.x * blockDim.x + threadIdx.x) >> 5;
    int lane = threadIdx.x & 31;
    if (wg >= n) return;
    int c = wg;
    int s = g_estart[c], e = g_estart[c + 1];

    float2 acc = make_float2(0.f, 0.f);
    int base = s;
    for (; base + 32 <= e; base += 32) {
        int idx = g_srow[base + lane];
#pragma unroll
        for (int j = 0; j < 32; j++) {
            int r = __shfl_sync(~0u, idx, j);
            float2 v = *(const float2*)&g_y[(size_t)r * 64 + lane * 2];
            acc.x += v.x; acc.y += v.y;
        }
    }
    if (base < e) {
        int m = e - base;
        int idx = (lane < m) ? g_srow[base + lane] : 0;
        for (int j = 0; j < m; j++) {
            int r = __shfl_sync(~0u, idx, j);
            float2 v = *(const float2*)&g_y[(size_t)r * 64 + lane * 2];
            acc.x += v.x; acc.y += v.y;
        }
    }

    float dc = g_dis[c];
    float d2 = dc * dc;
    size_t bofs = (size_t)c * 64 + lane * 2;
    float2 xw = *(const float2*)&g_xw1[bofs];
    float2 bb = *(const float2*)&b1[lane * 2];
    float v0 = tanhf(acc.x * dc + xw.x * d2 + bb.x);
    float v1 = tanhf(acc.y * dc + xw.y * d2 + bb.y);
    *(float2*)&g_x1[bofs] = make_float2(v0, v1);

    float2 w2 = *(const float2*)&W2[lane * 2];
    float dot = v0 * w2.x + v1 * w2.y;
#pragma unroll
    for (int off = 16; off; off >>= 1) dot += __shfl_xor_sync(~0u, dot, off);
    if (lane == 0) {
        g_xw2[c] = dot;
        g_z[c] = dot * dc;
    }
}

// ---------------- K7: gather-aggregate conv2 + tanh (fused) -----------------
__global__ void agg2_gather_kernel(const float* __restrict__ b2, int n) {
    int wg = (blockIdx.x * blockDim.x + threadIdx.x) >> 5;
    int lane = threadIdx.x & 31;
    if (wg >= n) return;
    int c = wg;
    int s = g_estart[c], e = g_estart[c + 1];
    float sum = 0.f;
    for (int i = s + lane; i < e; i += 32) {
        int r = g_srow[i];
        sum += g_z[r];
    }
#pragma unroll
    for (int off = 16; off; off >>= 1) sum += __shfl_xor_sync(~0u, sum, off);
    if (lane == 0) {
        float dc = g_dis[c];
        g_x2[c] = tanhf(sum * dc + g_xw2[c] * dc * dc + b2[0]);
    }
}

// ---------------- K8: exclusive scan of graph counts ------------------------
__global__ void scan_kernel(int B) {
    __shared__ int s[BMAX];
    int t = threadIdx.x;
    int v = (t < B) ? g_cnt[t] : 0;
    s[t] = v;
    __syncthreads();
    for (int off = 1; off < BMAX; off <<= 1) {
        int u = (t >= off) ? s[t - off] : 0;
        __syncthreads();
        s[t] += u;
        __syncthreads();
    }
    if (t < B) g_start[t] = s[t] - v;
}

// ---------------- K9: fused sort-pool(top-30) + CNN head + MLP + logsoftmax -
__global__ void head_kernel(const float* __restrict__ w3, const float* __restrict__ b3,
                            const float* __restrict__ w4, const float* __restrict__ b4,
                            const float* __restrict__ fw1, const float* __restrict__ fb1,
                            const float* __restrict__ fw2, const float* __restrict__ fb2,
                            float* __restrict__ out, int B) {
    __shared__ float sc[SEGMAX];
    __shared__ int sel[KTOP];
    __shared__ float p[PLEN];
    __shared__ float c3[320];
    __shared__ float pl[160];
    __shared__ float h[192];
    __shared__ float ll[128];
    __shared__ float o[18];
    __shared__ unsigned long long redk[256];

    int g = blockIdx.x;
    int t = threadIdx.x;
    int start = g_start[g];
    int cnt = min(g_cnt[g], SEGMAX);
    int ksel = min(cnt, KTOP);

    for (int i = t; i < cnt; i += 256) sc[i] = g_x2[start + i];
    __syncthreads();

    for (int j = 0; j < ksel; j++) {
        unsigned long long best = 0ull;
        for (int i = t; i < cnt; i += 256) {
            unsigned u = __float_as_uint(sc[i]);
            u = (u & 0x80000000u) ? ~u : (u | 0x80000000u);
            unsigned long long key =
                ((unsigned long long)u << 32) | (unsigned)(~i);
            if (key > best) best = key;
        }
        redk[t] = best;
        __syncthreads();
        for (int off = 128; off; off >>= 1) {
            if (t < off) redk[t] = max(redk[t], redk[t + off]);
            __syncthreads();
        }
        int pos = (int)(~(unsigned)(redk[0] & 0xFFFFFFFFull));
        if (t == 0) {
            sel[j] = start + pos;
            sc[pos] = -CUDART_INF_F;
        }
        __syncthreads();
    }

    for (int idx = t; idx < PLEN; idx += 256) {
        int j = idx / 65, c = idx % 65;
        float v = 0.f;
        if (j < ksel) {
            int node = sel[j];
            v = (c < 64) ? g_x1[(size_t)node * 64 + c] : g_x2[node];
        }
        p[idx] = v;
    }
    __syncthreads();

    for (int idx = t; idx < 320; idx += 256) {
        int oc = idx / 20, tt = idx % 20;
        float s = b3[oc];
        const float* w = w3 + oc * 97;
        const float* pp = p + tt * 97;
#pragma unroll 1
        for (int i = 0; i < 97; i++) s += pp[i] * w[i];
        c3[oc * 20 + tt] = fmaxf(s, 0.f);
    }
    __syncthreads();

    for (int idx = t; idx < 160; idx += 256) {
        int oc = idx / 10, tt = idx % 10;
        pl[idx] = fmaxf(c3[oc * 20 + 2 * tt], c3[oc * 20 + 2 * tt + 1]);
    }
    __syncthreads();

    for (int idx = t; idx < 192; idx += 256) {
        int oc = idx / 6, tt = idx % 6;
        float s = b4[oc];
#pragma unroll
        for (int ic = 0; ic < 16; ic++)
#pragma unroll
            for (int i = 0; i < 5; i++)
                s += pl[ic * 10 + tt + i] * w4[oc * 80 + ic * 5 + i];
        h[idx] = fmaxf(s, 0.f);
    }
    __syncthreads();

    for (int j = t; j < 128; j += 256) {
        float s = fb1[j];
#pragma unroll 4
        for (int i = 0; i < 192; i++) s += h[i] * fw1[i * 128 + j];
        float r = fmaxf(s, 0.f);
        ll[j] = r;
        out[(size_t)2 * B * 18 + (size_t)g * 128 + j] = r;
    }
    __syncthreads();

    for (int j = t; j < 18; j += 256) {
        float s = fb2[j];
#pragma unroll 4
        for (int i = 0; i < 128; i++) s += ll[i] * fw2[i * 18 + j];
        o[j] = s;
        out[(size_t)B * 18 + (size_t)g * 18 + j] = s;
    }
    __syncthreads();

    if (t == 0) {
        float m = o[0];
        for (int j = 1; j < 18; j++) m = fmaxf(m, o[j]);
        float se = 0.f;
        for (int j = 0; j < 18; j++) se += expf(o[j] - m);
        float lse = logf(se) + m;
        for (int j = 0; j < 18; j++) out[(size_t)g * 18 + j] = o[j] - lse;
    }
}

// ---------------- launch ----------------------------------------------------
extern "C" void kernel_launch(void* const* d_in, const int* in_sizes, int n_in,
                              void* d_out, int out_size) {
    const float* x    = (const float*)d_in[0];
    const int* ei     = (const int*)d_in[1];
    const int* batch  = (const int*)d_in[2];
    const float* W1   = (const float*)d_in[4];
    const float* b1   = (const float*)d_in[5];
    const float* W2   = (const float*)d_in[6];
    const float* b2   = (const float*)d_in[7];
    const float* w3   = (const float*)d_in[8];
    const float* b3   = (const float*)d_in[9];
    const float* w4   = (const float*)d_in[10];
    const float* b4   = (const float*)d_in[11];
    const float* fw1  = (const float*)d_in[12];
    const float* fb1  = (const float*)d_in[13];
    const float* fw2  = (const float*)d_in[14];
    const float* fb2  = (const float*)d_in[15];
    float* out = (float*)d_out;

    int n = in_sizes[0] / 128;
    int E = in_sizes[1] / 2;
    int B = out_size / 164;
    const int* row = ei;
    const int* col = ei + E;

    void* pa;
    cudaGetSymbolAddress(&pa, g_indeg);
    cudaMemsetAsync(pa, 0, (size_t)n * sizeof(int), 0);
    cudaGetSymbolAddress(&pa, g_cnt);
    cudaMemsetAsync(pa, 0, (size_t)B * sizeof(int), 0);

    cudaFuncSetAttribute(gemm1_kernel,
                         cudaFuncAttributeMaxDynamicSharedMemorySize, GEMM_SMEM);
    gemm1_kernel<<<(n + GEMM_TR - 1) / GEMM_TR, 256, GEMM_SMEM>>>(x, W1, n);

    indeg_kernel<<<(E + 255) / 256, 256>>>(row, col, E);
    node_scan_kernel<<<1, 1024>>>(n);
    scatter_kernel<<<(E + 255) / 256, 256>>>(row, col, E);
    prep_kernel<<<(n * 16 + 255) / 256, 256>>>(batch, n);

    agg1_gather_kernel<<<(n * 32 + 255) / 256, 256>>>(b1, W2, n);
    agg2_gather_kernel<<<(n * 32 + 255) / 256, 256>>>(b2, n);

    scan_kernel<<<1, BMAX>>>(B);
    head_kernel<<<B, 256>>>(w3, b3, w4, b4, fw1, fb1, fw2, fb2, out, B);
}

// round 4
// speedup vs baseline: 1.1470x; 1.1470x over previous
#include <cuda_runtime.h>
#include <cstdint>
#include <math_constants.h>

#define NMAX 100000
#define CH 64
#define BMAX 512
#define KTOP 30
#define PLEN 1950   // 30 * 65
#define SEGMAX 4096

// ---------------- scratch (static device globals; no allocs allowed) -------
__device__ float g_y[NMAX * CH];     // (x @ W1) * dis[row]  (fp32)
__device__ float g_agg1[NMAX * CH];  // sum of y over incoming edges
__device__ float g_x1[NMAX * CH];
__device__ float g_deg[NMAX];
__device__ float g_dis[NMAX];
__device__ float g_z[NMAX];          // (x1 @ W2) * dis[row]
__device__ float g_agg2[NMAX];
__device__ float g_x2[NMAX];
__device__ int   g_cnt[BMAX];
__device__ int   g_start[BMAX];

// ---------------- K1: degree counts over edges ------------------------------
__global__ void deg_kernel(const int* __restrict__ row,
                           const int* __restrict__ col, int E) {
    int e = blockIdx.x * blockDim.x + threadIdx.x;
    if (e >= E) return;
    int r = row[e], c = col[e];
    if (r != c) atomicAdd(&g_deg[c], 1.0f);
}

// ---------------- K2: dis = rsqrt(deg + 1) ----------------------------------
__global__ void dis_kernel(int n) {
    int i = blockIdx.x * blockDim.x + threadIdx.x;
    if (i < n) g_dis[i] = rsqrtf(g_deg[i] + 1.0f);
}

// ---------------- K3: y = (x @ W1) * dis[row] -------------------------------
#define GEMM_TR 128
#define XPITCH 132
#define GEMM_SMEM ((GEMM_TR * XPITCH + 128 * 64) * 4)

__global__ void gemm1_kernel(const float* __restrict__ x,
                             const float* __restrict__ W, int n) {
    extern __shared__ float smem[];
    float* xs = smem;                       // [128][132]
    float* ws = smem + GEMM_TR * XPITCH;    // [128][64]
    int t = threadIdx.x;
    int row0 = blockIdx.x * GEMM_TR;

    for (int i = t; i < 128 * 64 / 4; i += 256)
        ((float4*)ws)[i] = ((const float4*)W)[i];
    for (int i = t; i < GEMM_TR * 32; i += 256) {
        int r = i >> 5, c4 = i & 31;
        float4 v = make_float4(0.f, 0.f, 0.f, 0.f);
        if (row0 + r < n) v = ((const float4*)x)[(size_t)(row0 + r) * 32 + c4];
        *(float4*)&xs[r * XPITCH + c4 * 4] = v;
    }
    __syncthreads();

    int tx = t & 7;
    int ty = t >> 3;
    float acc[4][8];
#pragma unroll
    for (int i = 0; i < 4; i++)
#pragma unroll
        for (int j = 0; j < 8; j++) acc[i][j] = 0.f;

#pragma unroll 4
    for (int k = 0; k < 128; k++) {
        float4 b0 = *(float4*)&ws[k * 64 + tx * 8];
        float4 b1 = *(float4*)&ws[k * 64 + tx * 8 + 4];
        float bb[8] = {b0.x, b0.y, b0.z, b0.w, b1.x, b1.y, b1.z, b1.w};
        float aa[4];
#pragma unroll
        for (int i = 0; i < 4; i++) aa[i] = xs[(ty * 4 + i) * XPITCH + k];
#pragma unroll
        for (int i = 0; i < 4; i++)
#pragma unroll
            for (int j = 0; j < 8; j++) acc[i][j] += aa[i] * bb[j];
    }

#pragma unroll
    for (int i = 0; i < 4; i++) {
        int r = row0 + ty * 4 + i;
        if (r < n) {
            float d = g_dis[r];
            *(float4*)&g_y[(size_t)r * 64 + tx * 8] =
                make_float4(acc[i][0] * d, acc[i][1] * d,
                            acc[i][2] * d, acc[i][3] * d);
            *(float4*)&g_y[(size_t)r * 64 + tx * 8 + 4] =
                make_float4(acc[i][4] * d, acc[i][5] * d,
                            acc[i][6] * d, acc[i][7] * d);
        }
    }
}

// ---------------- K4: edge aggregation conv1 (pure LDG.128 + RED.128) -------
__global__ void agg1_kernel(const int* __restrict__ row,
                            const int* __restrict__ col, int E) {
    int t = blockIdx.x * blockDim.x + threadIdx.x;
    int e = t >> 4;
    int sub = t & 15;
    if (e >= E) return;
    int r = __ldg(row + e), c = __ldg(col + e);
    if (r == c) return;
    float4 v = *(const float4*)&g_y[(size_t)r * 64 + sub * 4];
    atomicAdd((float4*)&g_agg1[(size_t)c * 64 + sub * 4], v);
}

// ---------------- K5: x1 = tanh(dis*(agg1 + y) + b1); z = (x1.W2)*dis -------
__global__ void node1_kernel(const float* __restrict__ W2,
                             const float* __restrict__ b1, int n) {
    int gt = blockIdx.x * blockDim.x + threadIdx.x;
    int node = gt >> 5;
    int lane = gt & 31;
    if (node >= n) return;
    float dc = g_dis[node];
    size_t base = (size_t)node * 64 + lane * 2;
    float2 yv = *(const float2*)&g_y[base];
    float2 ag = *(const float2*)&g_agg1[base];
    float2 bb = *(const float2*)&b1[lane * 2];
    float v0 = tanhf((ag.x + yv.x) * dc + bb.x);
    float v1 = tanhf((ag.y + yv.y) * dc + bb.y);
    *(float2*)&g_x1[base] = make_float2(v0, v1);
    float2 w2 = *(const float2*)&W2[lane * 2];
    float dot = v0 * w2.x + v1 * w2.y;
#pragma unroll
    for (int off = 16; off; off >>= 1) dot += __shfl_xor_sync(~0u, dot, off);
    if (lane == 0) g_z[node] = dot * dc;
}

// ---------------- K6: edge aggregation conv2 (scalar gather + RED) ----------
__global__ void agg2_kernel(const int* __restrict__ row,
                            const int* __restrict__ col, int E) {
    int e = blockIdx.x * blockDim.x + threadIdx.x;
    if (e >= E) return;
    int r = row[e], c = col[e];
    if (r == c) return;
    atomicAdd(&g_agg2[c], g_z[r]);
}

// ---------------- K7: x2 = tanh(dis*(agg2 + z) + b2); batch counts ----------
__global__ void node2_kernel(const float* __restrict__ b2,
                             const int* __restrict__ batch, int n) {
    int i = blockIdx.x * blockDim.x + threadIdx.x;
    if (i >= n) return;
    float dc = g_dis[i];
    g_x2[i] = tanhf((g_agg2[i] + g_z[i]) * dc + b2[0]);
    atomicAdd(&g_cnt[batch[i]], 1);
}

// ---------------- K8: exclusive scan of counts -> segment starts ------------
__global__ void scan_kernel(int B) {
    __shared__ int s[BMAX];
    int t = threadIdx.x;
    int v = (t < B) ? g_cnt[t] : 0;
    s[t] = v;
    __syncthreads();
    for (int off = 1; off < BMAX; off <<= 1) {
        int u = (t >= off) ? s[t - off] : 0;
        __syncthreads();
        s[t] += u;
        __syncthreads();
    }
    if (t < B) g_start[t] = s[t] - v;
}

// ---------------- K9: fused sort-pool(top-30) + CNN head + MLP + logsoftmax -
__global__ void head_kernel(const float* __restrict__ w3, const float* __restrict__ b3,
                            const float* __restrict__ w4, const float* __restrict__ b4,
                            const float* __restrict__ fw1, const float* __restrict__ fb1,
                            const float* __restrict__ fw2, const float* __restrict__ fb2,
                            float* __restrict__ out, int B) {
    __shared__ float sc[SEGMAX];
    __shared__ int sel[KTOP];
    __shared__ float p[PLEN];
    __shared__ float c3[320];
    __shared__ float pl[160];
    __shared__ float h[192];
    __shared__ float ll[128];
    __shared__ float o[18];
    __shared__ unsigned long long redk[256];

    int g = blockIdx.x;
    int t = threadIdx.x;
    int start = g_start[g];
    int cnt = min(g_cnt[g], SEGMAX);
    int ksel = min(cnt, KTOP);

    for (int i = t; i < cnt; i += 256) sc[i] = g_x2[start + i];
    __syncthreads();

    // iterative stable top-K: max score, tie -> lowest index (matches lexsort)
    for (int j = 0; j < ksel; j++) {
        unsigned long long best = 0ull;
        for (int i = t; i < cnt; i += 256) {
            unsigned u = __float_as_uint(sc[i]);
            u = (u & 0x80000000u) ? ~u : (u | 0x80000000u);
            unsigned long long key =
                ((unsigned long long)u << 32) | (unsigned)(~i);
            if (key > best) best = key;
        }
        redk[t] = best;
        __syncthreads();
        for (int off = 128; off; off >>= 1) {
            if (t < off) redk[t] = max(redk[t], redk[t + off]);
            __syncthreads();
        }
        int pos = (int)(~(unsigned)(redk[0] & 0xFFFFFFFFull));
        if (t == 0) {
            sel[j] = start + pos;
            sc[pos] = -CUDART_INF_F;
        }
        __syncthreads();
    }

    for (int idx = t; idx < PLEN; idx += 256) {
        int j = idx / 65, c = idx % 65;
        float v = 0.f;
        if (j < ksel) {
            int node = sel[j];
            v = (c < 64) ? g_x1[(size_t)node * 64 + c] : g_x2[node];
        }
        p[idx] = v;
    }
    __syncthreads();

    for (int idx = t; idx < 320; idx += 256) {
        int oc = idx / 20, tt = idx % 20;
        float s = b3[oc];
        const float* w = w3 + oc * 97;
        const float* pp = p + tt * 97;
#pragma unroll 1
        for (int i = 0; i < 97; i++) s += pp[i] * w[i];
        c3[oc * 20 + tt] = fmaxf(s, 0.f);
    }
    __syncthreads();

    for (int idx = t; idx < 160; idx += 256) {
        int oc = idx / 10, tt = idx % 10;
        pl[idx] = fmaxf(c3[oc * 20 + 2 * tt], c3[oc * 20 + 2 * tt + 1]);
    }
    __syncthreads();

    for (int idx = t; idx < 192; idx += 256) {
        int oc = idx / 6, tt = idx % 6;
        float s = b4[oc];
#pragma unroll
        for (int ic = 0; ic < 16; ic++)
#pragma unroll
            for (int i = 0; i < 5; i++)
                s += pl[ic * 10 + tt + i] * w4[oc * 80 + ic * 5 + i];
        h[idx] = fmaxf(s, 0.f);
    }
    __syncthreads();

    for (int j = t; j < 128; j += 256) {
        float s = fb1[j];
#pragma unroll 4
        for (int i = 0; i < 192; i++) s += h[i] * fw1[i * 128 + j];
        float r = fmaxf(s, 0.f);
        ll[j] = r;
        out[(size_t)2 * B * 18 + (size_t)g * 128 + j] = r;
    }
    __syncthreads();

    for (int j = t; j < 18; j += 256) {
        float s = fb2[j];
#pragma unroll 4
        for (int i = 0; i < 128; i++) s += ll[i] * fw2[i * 18 + j];
        o[j] = s;
        out[(size_t)B * 18 + (size_t)g * 18 + j] = s;
    }
    __syncthreads();

    if (t == 0) {
        float m = o[0];
        for (int j = 1; j < 18; j++) m = fmaxf(m, o[j]);
        float se = 0.f;
        for (int j = 0; j < 18; j++) se += expf(o[j] - m);
        float lse = logf(se) + m;
        for (int j = 0; j < 18; j++) out[(size_t)g * 18 + j] = o[j] - lse;
    }
}

// ---------------- launch ----------------------------------------------------
extern "C" void kernel_launch(void* const* d_in, const int* in_sizes, int n_in,
                              void* d_out, int out_size) {
    const float* x    = (const float*)d_in[0];
    const int* ei     = (const int*)d_in[1];
    const int* batch  = (const int*)d_in[2];
    const float* W1   = (const float*)d_in[4];
    const float* b1   = (const float*)d_in[5];
    const float* W2   = (const float*)d_in[6];
    const float* b2   = (const float*)d_in[7];
    const float* w3   = (const float*)d_in[8];
    const float* b3   = (const float*)d_in[9];
    const float* w4   = (const float*)d_in[10];
    const float* b4   = (const float*)d_in[11];
    const float* fw1  = (const float*)d_in[12];
    const float* fb1  = (const float*)d_in[13];
    const float* fw2  = (const float*)d_in[14];
    const float* fb2  = (const float*)d_in[15];
    float* out = (float*)d_out;

    int n = in_sizes[0] / 128;
    int E = in_sizes[1] / 2;
    int B = out_size / 164;   // 18 + 18 + 128
    const int* row = ei;
    const int* col = ei + E;

    void* pa;
    cudaGetSymbolAddress(&pa, g_agg1);
    cudaMemsetAsync(pa, 0, (size_t)n * 64 * sizeof(float), 0);
    cudaGetSymbolAddress(&pa, g_agg2);
    cudaMemsetAsync(pa, 0, (size_t)n * sizeof(float), 0);
    cudaGetSymbolAddress(&pa, g_deg);
    cudaMemsetAsync(pa, 0, (size_t)n * sizeof(float), 0);
    cudaGetSymbolAddress(&pa, g_cnt);
    cudaMemsetAsync(pa, 0, (size_t)B * sizeof(int), 0);

    deg_kernel<<<(E + 255) / 256, 256>>>(row, col, E);
    dis_kernel<<<(n + 255) / 256, 256>>>(n);

    cudaFuncSetAttribute(gemm1_kernel,
                         cudaFuncAttributeMaxDynamicSharedMemorySize, GEMM_SMEM);
    gemm1_kernel<<<(n + GEMM_TR - 1) / GEMM_TR, 256, GEMM_SMEM>>>(x, W1, n);

    {
        long long tot = (long long)E * 16;
        int blocks = (int)((tot + 255) / 256);
        agg1_kernel<<<blocks, 256>>>(row, col, E);
    }

    node1_kernel<<<(n * 32 + 255) / 256, 256>>>(W2, b1, n);
    agg2_kernel<<<(E + 255) / 256, 256>>>(row, col, E);
    node2_kernel<<<(n + 255) / 256, 256>>>(b2, batch, n);
    scan_kernel<<<1, BMAX>>>(B);
    head_kernel<<<B, 256>>>(w3, b3, w4, b4, fw1, fb1, fw2, fb2, out, B);
}

// round 5
// speedup vs baseline: 1.2733x; 1.1101x over previous
#include <cuda_runtime.h>
#include <cstdint>
#include <math_constants.h>

#define NMAX 100000
#define CH 64
#define BMAX 512
#define KTOP 30
#define PLEN 1950   // 30 * 65
#define SEGMAX 4096

// ---------------- scratch (static device globals; no allocs allowed) -------
__device__ float g_y[NMAX * CH];     // (x @ W1) * dis[row]  (fp32)
__device__ float g_agg1[NMAX * CH];  // sum of y over incoming edges
__device__ float g_x1[NMAX * CH];
__device__ float g_deg[NMAX];
__device__ float g_dis[NMAX];
__device__ float g_z[NMAX];          // (x1 @ W2) * dis[row]
__device__ float g_agg2[NMAX];
__device__ float g_x2[NMAX];
__device__ int   g_cnt[BMAX];
__device__ int   g_start[BMAX];

// ---------------- K1: degree counts (4-edge batched) ------------------------
__global__ void deg_kernel(const int* __restrict__ row,
                           const int* __restrict__ col, int E) {
    int g = blockIdx.x * blockDim.x + threadIdx.x;
    int e0 = g * 4;
    if (e0 >= E) return;
    int rr[4], cc[4];
    if (e0 + 3 < E) {
        int4 r4 = __ldg((const int4*)row + g);
        int4 c4 = __ldg((const int4*)col + g);
        rr[0] = r4.x; rr[1] = r4.y; rr[2] = r4.z; rr[3] = r4.w;
        cc[0] = c4.x; cc[1] = c4.y; cc[2] = c4.z; cc[3] = c4.w;
    } else {
#pragma unroll
        for (int k = 0; k < 4; k++) {
            int e = e0 + k;
            rr[k] = (e < E) ? row[e] : 0;
            cc[k] = (e < E) ? col[e] : 0;
        }
    }
#pragma unroll
    for (int k = 0; k < 4; k++)
        if (rr[k] != cc[k]) atomicAdd(&g_deg[cc[k]], 1.0f);
}

// ---------------- K2: dis = rsqrt(deg + 1) ----------------------------------
__global__ void dis_kernel(int n) {
    int i = blockIdx.x * blockDim.x + threadIdx.x;
    if (i < n) g_dis[i] = rsqrtf(g_deg[i] + 1.0f);
}

// ---------------- K3: y = (x @ W1) * dis[row] -------------------------------
#define GEMM_TR 128
#define XPITCH 132
#define GEMM_SMEM ((GEMM_TR * XPITCH + 128 * 64) * 4)

__global__ void gemm1_kernel(const float* __restrict__ x,
                             const float* __restrict__ W, int n) {
    extern __shared__ float smem[];
    float* xs = smem;                       // [128][132]
    float* ws = smem + GEMM_TR * XPITCH;    // [128][64]
    int t = threadIdx.x;
    int row0 = blockIdx.x * GEMM_TR;

    for (int i = t; i < 128 * 64 / 4; i += 256)
        ((float4*)ws)[i] = ((const float4*)W)[i];
    for (int i = t; i < GEMM_TR * 32; i += 256) {
        int r = i >> 5, c4 = i & 31;
        float4 v = make_float4(0.f, 0.f, 0.f, 0.f);
        if (row0 + r < n) v = ((const float4*)x)[(size_t)(row0 + r) * 32 + c4];
        *(float4*)&xs[r * XPITCH + c4 * 4] = v;
    }
    __syncthreads();

    int tx = t & 7;
    int ty = t >> 3;
    float acc[4][8];
#pragma unroll
    for (int i = 0; i < 4; i++)
#pragma unroll
        for (int j = 0; j < 8; j++) acc[i][j] = 0.f;

#pragma unroll 4
    for (int k = 0; k < 128; k++) {
        float4 b0 = *(float4*)&ws[k * 64 + tx * 8];
        float4 b1 = *(float4*)&ws[k * 64 + tx * 8 + 4];
        float bb[8] = {b0.x, b0.y, b0.z, b0.w, b1.x, b1.y, b1.z, b1.w};
        float aa[4];
#pragma unroll
        for (int i = 0; i < 4; i++) aa[i] = xs[(ty * 4 + i) * XPITCH + k];
#pragma unroll
        for (int i = 0; i < 4; i++)
#pragma unroll
            for (int j = 0; j < 8; j++) acc[i][j] += aa[i] * bb[j];
    }

#pragma unroll
    for (int i = 0; i < 4; i++) {
        int r = row0 + ty * 4 + i;
        if (r < n) {
            float d = g_dis[r];
            *(float4*)&g_y[(size_t)r * 64 + tx * 8] =
                make_float4(acc[i][0] * d, acc[i][1] * d,
                            acc[i][2] * d, acc[i][3] * d);
            *(float4*)&g_y[(size_t)r * 64 + tx * 8 + 4] =
                make_float4(acc[i][4] * d, acc[i][5] * d,
                            acc[i][6] * d, acc[i][7] * d);
        }
    }
}

// ---------------- K4: edge aggregation conv1 (4-edge batched, MLP=4) --------
__global__ void agg1_kernel(const int* __restrict__ row,
                            const int* __restrict__ col, int E) {
    int t = blockIdx.x * blockDim.x + threadIdx.x;
    int g = t >> 4;           // 4-edge group
    int sub = t & 15;         // 16B chunk within the 64-ch row
    int e0 = g * 4;
    if (e0 >= E) return;

    int rr[4], cc[4];
    if (e0 + 3 < E) {
        int4 r4 = __ldg((const int4*)row + g);
        int4 c4 = __ldg((const int4*)col + g);
        rr[0] = r4.x; rr[1] = r4.y; rr[2] = r4.z; rr[3] = r4.w;
        cc[0] = c4.x; cc[1] = c4.y; cc[2] = c4.z; cc[3] = c4.w;
    } else {
#pragma unroll
        for (int k = 0; k < 4; k++) {
            int e = e0 + k;
            rr[k] = (e < E) ? __ldg(row + e) : 0;
            cc[k] = (e < E) ? __ldg(col + e) : 0;
        }
    }

    const float4* yb = (const float4*)g_y;
    float4 v[4];
    bool p[4];
#pragma unroll
    for (int k = 0; k < 4; k++) {
        p[k] = (rr[k] != cc[k]);
        if (p[k]) v[k] = __ldg(yb + (size_t)rr[k] * 16 + sub);
    }
#pragma unroll
    for (int k = 0; k < 4; k++) {
        if (p[k])
            atomicAdd((float4*)&g_agg1[(size_t)cc[k] * 64 + sub * 4], v[k]);
    }
}

// ---------------- K5: x1 = tanh(dis*(agg1 + y) + b1); z = (x1.W2)*dis -------
__global__ void node1_kernel(const float* __restrict__ W2,
                             const float* __restrict__ b1, int n) {
    int gt = blockIdx.x * blockDim.x + threadIdx.x;
    int node = gt >> 5;
    int lane = gt & 31;
    if (node >= n) return;
    float dc = g_dis[node];
    size_t base = (size_t)node * 64 + lane * 2;
    float2 yv = *(const float2*)&g_y[base];
    float2 ag = *(const float2*)&g_agg1[base];
    float2 bb = *(const float2*)&b1[lane * 2];
    float v0 = tanhf((ag.x + yv.x) * dc + bb.x);
    float v1 = tanhf((ag.y + yv.y) * dc + bb.y);
    *(float2*)&g_x1[base] = make_float2(v0, v1);
    float2 w2 = *(const float2*)&W2[lane * 2];
    float dot = v0 * w2.x + v1 * w2.y;
#pragma unroll
    for (int off = 16; off; off >>= 1) dot += __shfl_xor_sync(~0u, dot, off);
    if (lane == 0) g_z[node] = dot * dc;
}

// ---------------- K6: edge aggregation conv2 (4-edge batched, MLP=4) --------
__global__ void agg2_kernel(const int* __restrict__ row,
                            const int* __restrict__ col, int E) {
    int g = blockIdx.x * blockDim.x + threadIdx.x;
    int e0 = g * 4;
    if (e0 >= E) return;
    int rr[4], cc[4];
    if (e0 + 3 < E) {
        int4 r4 = __ldg((const int4*)row + g);
        int4 c4 = __ldg((const int4*)col + g);
        rr[0] = r4.x; rr[1] = r4.y; rr[2] = r4.z; rr[3] = r4.w;
        cc[0] = c4.x; cc[1] = c4.y; cc[2] = c4.z; cc[3] = c4.w;
    } else {
#pragma unroll
        for (int k = 0; k < 4; k++) {
            int e = e0 + k;
            rr[k] = (e < E) ? row[e] : 0;
            cc[k] = (e < E) ? col[e] : 0;
        }
    }
    float zv[4];
    bool p[4];
#pragma unroll
    for (int k = 0; k < 4; k++) {
        p[k] = (rr[k] != cc[k]);
        if (p[k]) zv[k] = __ldg(&g_z[rr[k]]);
    }
#pragma unroll
    for (int k = 0; k < 4; k++)
        if (p[k]) atomicAdd(&g_agg2[cc[k]], zv[k]);
}

// ---------------- K7: x2 = tanh(dis*(agg2 + z) + b2); batch counts ----------
__global__ void node2_kernel(const float* __restrict__ b2,
                             const int* __restrict__ batch, int n) {
    int i = blockIdx.x * blockDim.x + threadIdx.x;
    if (i >= n) return;
    float dc = g_dis[i];
    g_x2[i] = tanhf((g_agg2[i] + g_z[i]) * dc + b2[0]);
    atomicAdd(&g_cnt[batch[i]], 1);
}

// ---------------- K8: exclusive scan of counts -> segment starts ------------
__global__ void scan_kernel(int B) {
    __shared__ int s[BMAX];
    int t = threadIdx.x;
    int v = (t < B) ? g_cnt[t] : 0;
    s[t] = v;
    __syncthreads();
    for (int off = 1; off < BMAX; off <<= 1) {
        int u = (t >= off) ? s[t - off] : 0;
        __syncthreads();
        s[t] += u;
        __syncthreads();
    }
    if (t < B) g_start[t] = s[t] - v;
}

// ---------------- K9: fused sort-pool(top-30) + CNN head + MLP + logsoftmax -
__global__ void head_kernel(const float* __restrict__ w3, const float* __restrict__ b3,
                            const float* __restrict__ w4, const float* __restrict__ b4,
                            const float* __restrict__ fw1, const float* __restrict__ fb1,
                            const float* __restrict__ fw2, const float* __restrict__ fb2,
                            float* __restrict__ out, int B) {
    __shared__ float sc[SEGMAX];
    __shared__ int sel[KTOP];
    __shared__ float p[PLEN];
    __shared__ float c3[320];
    __shared__ float pl[160];
    __shared__ float h[192];
    __shared__ float ll[128];
    __shared__ float o[18];
    __shared__ unsigned long long redk[256];

    int g = blockIdx.x;
    int t = threadIdx.x;
    int start = g_start[g];
    int cnt = min(g_cnt[g], SEGMAX);
    int ksel = min(cnt, KTOP);

    for (int i = t; i < cnt; i += 256) sc[i] = g_x2[start + i];
    __syncthreads();

    // iterative stable top-K: max score, tie -> lowest index (matches lexsort)
    for (int j = 0; j < ksel; j++) {
        unsigned long long best = 0ull;
        for (int i = t; i < cnt; i += 256) {
            unsigned u = __float_as_uint(sc[i]);
            u = (u & 0x80000000u) ? ~u : (u | 0x80000000u);
            unsigned long long key =
                ((unsigned long long)u << 32) | (unsigned)(~i);
            if (key > best) best = key;
        }
        redk[t] = best;
        __syncthreads();
        for (int off = 128; off; off >>= 1) {
            if (t < off) redk[t] = max(redk[t], redk[t + off]);
            __syncthreads();
        }
        int pos = (int)(~(unsigned)(redk[0] & 0xFFFFFFFFull));
        if (t == 0) {
            sel[j] = start + pos;
            sc[pos] = -CUDART_INF_F;
        }
        __syncthreads();
    }

    for (int idx = t; idx < PLEN; idx += 256) {
        int j = idx / 65, c = idx % 65;
        float v = 0.f;
        if (j < ksel) {
            int node = sel[j];
            v = (c < 64) ? g_x1[(size_t)node * 64 + c] : g_x2[node];
        }
        p[idx] = v;
    }
    __syncthreads();

    for (int idx = t; idx < 320; idx += 256) {
        int oc = idx / 20, tt = idx % 20;
        float s = b3[oc];
        const float* w = w3 + oc * 97;
        const float* pp = p + tt * 97;
#pragma unroll 1
        for (int i = 0; i < 97; i++) s += pp[i] * w[i];
        c3[oc * 20 + tt] = fmaxf(s, 0.f);
    }
    __syncthreads();

    for (int idx = t; idx < 160; idx += 256) {
        int oc = idx / 10, tt = idx % 10;
        pl[idx] = fmaxf(c3[oc * 20 + 2 * tt], c3[oc * 20 + 2 * tt + 1]);
    }
    __syncthreads();

    for (int idx = t; idx < 192; idx += 256) {
        int oc = idx / 6, tt = idx % 6;
        float s = b4[oc];
#pragma unroll
        for (int ic = 0; ic < 16; ic++)
#pragma unroll
            for (int i = 0; i < 5; i++)
                s += pl[ic * 10 + tt + i] * w4[oc * 80 + ic * 5 + i];
        h[idx] = fmaxf(s, 0.f);
    }
    __syncthreads();

    for (int j = t; j < 128; j += 256) {
        float s = fb1[j];
#pragma unroll 4
        for (int i = 0; i < 192; i++) s += h[i] * fw1[i * 128 + j];
        float r = fmaxf(s, 0.f);
        ll[j] = r;
        out[(size_t)2 * B * 18 + (size_t)g * 128 + j] = r;
    }
    __syncthreads();

    for (int j = t; j < 18; j += 256) {
        float s = fb2[j];
#pragma unroll 4
        for (int i = 0; i < 128; i++) s += ll[i] * fw2[i * 18 + j];
        o[j] = s;
        out[(size_t)B * 18 + (size_t)g * 18 + j] = s;
    }
    __syncthreads();

    if (t == 0) {
        float m = o[0];
        for (int j = 1; j < 18; j++) m = fmaxf(m, o[j]);
        float se = 0.f;
        for (int j = 0; j < 18; j++) se += expf(o[j] - m);
        float lse = logf(se) + m;
        for (int j = 0; j < 18; j++) out[(size_t)g * 18 + j] = o[j] - lse;
    }
}

// ---------------- launch ----------------------------------------------------
extern "C" void kernel_launch(void* const* d_in, const int* in_sizes, int n_in,
                              void* d_out, int out_size) {
    const float* x    = (const float*)d_in[0];
    const int* ei     = (const int*)d_in[1];
    const int* batch  = (const int*)d_in[2];
    const float* W1   = (const float*)d_in[4];
    const float* b1   = (const float*)d_in[5];
    const float* W2   = (const float*)d_in[6];
    const float* b2   = (const float*)d_in[7];
    const float* w3   = (const float*)d_in[8];
    const float* b3   = (const float*)d_in[9];
    const float* w4   = (const float*)d_in[10];
    const float* b4   = (const float*)d_in[11];
    const float* fw1  = (const float*)d_in[12];
    const float* fb1  = (const float*)d_in[13];
    const float* fw2  = (const float*)d_in[14];
    const float* fb2  = (const float*)d_in[15];
    float* out = (float*)d_out;

    int n = in_sizes[0] / 128;
    int E = in_sizes[1] / 2;
    int B = out_size / 164;   // 18 + 18 + 128
    const int* row = ei;
    const int* col = ei + E;
    int EG = (E + 3) / 4;     // 4-edge groups

    void* pa;
    cudaGetSymbolAddress(&pa, g_agg1);
    cudaMemsetAsync(pa, 0, (size_t)n * 64 * sizeof(float), 0);
    cudaGetSymbolAddress(&pa, g_agg2);
    cudaMemsetAsync(pa, 0, (size_t)n * sizeof(float), 0);
    cudaGetSymbolAddress(&pa, g_deg);
    cudaMemsetAsync(pa, 0, (size_t)n * sizeof(float), 0);
    cudaGetSymbolAddress(&pa, g_cnt);
    cudaMemsetAsync(pa, 0, (size_t)B * sizeof(int), 0);

    deg_kernel<<<(EG + 255) / 256, 256>>>(row, col, E);
    dis_kernel<<<(n + 255) / 256, 256>>>(n);

    cudaFuncSetAttribute(gemm1_kernel,
                         cudaFuncAttributeMaxDynamicSharedMemorySize, GEMM_SMEM);
    gemm1_kernel<<<(n + GEMM_TR - 1) / GEMM_TR, 256, GEMM_SMEM>>>(x, W1, n);

    {
        long long tot = (long long)EG * 16;
        int blocks = (int)((tot + 255) / 256);
        agg1_kernel<<<blocks, 256>>>(row, col, E);
    }

    node1_kernel<<<(n * 32 + 255) / 256, 256>>>(W2, b1, n);
    agg2_kernel<<<(EG + 255) / 256, 256>>>(row, col, E);
    node2_kernel<<<(n + 255) / 256, 256>>>(b2, batch, n);
    scan_kernel<<<1, BMAX>>>(B);
    head_kernel<<<B, 256>>>(w3, b3, w4, b4, fw1, fb1, fw2, fb2, out, B);
}